// round 1
// baseline (speedup 1.0000x reference)
#include <cuda_runtime.h>
#include <cuda_bf16.h>
#include <cstdint>
#include <cstddef>

// Problem constants
#define Bq   4
#define Sq   2048
#define Dq   1024
#define Hq   16
#define DHq  64
#define BSDq (Bq*Sq*Dq)   // 8388608

// Scratch (device globals: allocation-free rule)
__device__ float g_Q[BSDq];
__device__ float g_K[BSDq];
__device__ float g_V[BSDq];
__device__ float g_C[BSDq];   // context in [B,S,D] layout, input to FC
__device__ int   g_mask_kind; // 0=uint8, 1=int32, 2=float32

// ---------------------------------------------------------------------------
// Mask dtype sniffing: jax bool may arrive as uint8 (1B), int32, or float32.
// Values are 0/1 (or 0.0/1.0). Byte pattern over first 4KB distinguishes them.
// ---------------------------------------------------------------------------
__global__ void detect_mask_kernel(const unsigned char* __restrict__ m) {
    if (threadIdx.x != 0) return;
    int c0 = 0, c1 = 0, c2 = 0, c3 = 0;
    for (int i = 0; i < 4096; i += 4) {
        if (m[i + 0]) c0++;
        if (m[i + 1]) c1++;
        if (m[i + 2]) c2++;
        if (m[i + 3]) c3++;
    }
    int kind;
    if (c1 == 0 && c2 == 0 && c3 == 0) kind = 1;   // int32: 01 00 00 00
    else if (c0 == 0 && c1 == 0)       kind = 2;   // float32 1.0f: 00 00 80 3F
    else                               kind = 0;   // uint8 bool
    g_mask_kind = kind;
}

// ---------------------------------------------------------------------------
// out[M,N] = X[M,K] @ W[N,K]^T (+bias).  128x128x16 tile, 8x8 per thread.
// M,N multiples of 128; K multiple of 16.
// ---------------------------------------------------------------------------
__global__ __launch_bounds__(256, 2)
void gemm_nt_kernel(const float* __restrict__ X, const float* __restrict__ W,
                    const float* __restrict__ bias, float* __restrict__ out,
                    int M, int N, int K)
{
    __shared__ float Xs[16][132];
    __shared__ float Ws[16][132];
    const int tid = threadIdx.x;
    const int tx  = tid & 15;
    const int ty  = tid >> 4;
    const int m0  = blockIdx.y * 128;
    const int n0  = blockIdx.x * 128;

    float acc[8][8];
#pragma unroll
    for (int i = 0; i < 8; i++)
#pragma unroll
        for (int j = 0; j < 8; j++) acc[i][j] = 0.f;

    for (int k0 = 0; k0 < K; k0 += 16) {
#pragma unroll
        for (int l = 0; l < 2; l++) {
            int idx = l * 256 + tid;       // 0..511
            int row = idx >> 2;            // 0..127
            int kq  = (idx & 3) * 4;       // 0,4,8,12
            float4 xv = *(const float4*)(X + (size_t)(m0 + row) * K + k0 + kq);
            Xs[kq + 0][row] = xv.x; Xs[kq + 1][row] = xv.y;
            Xs[kq + 2][row] = xv.z; Xs[kq + 3][row] = xv.w;
            float4 wv = *(const float4*)(W + (size_t)(n0 + row) * K + k0 + kq);
            Ws[kq + 0][row] = wv.x; Ws[kq + 1][row] = wv.y;
            Ws[kq + 2][row] = wv.z; Ws[kq + 3][row] = wv.w;
        }
        __syncthreads();
#pragma unroll
        for (int kk = 0; kk < 16; kk++) {
            float a[8], b[8];
            *(float4*)(a)     = *(const float4*)&Xs[kk][ty * 8];
            *(float4*)(a + 4) = *(const float4*)&Xs[kk][ty * 8 + 4];
            *(float4*)(b)     = *(const float4*)&Ws[kk][tx * 8];
            *(float4*)(b + 4) = *(const float4*)&Ws[kk][tx * 8 + 4];
#pragma unroll
            for (int i = 0; i < 8; i++)
#pragma unroll
                for (int j = 0; j < 8; j++)
                    acc[i][j] += a[i] * b[j];
        }
        __syncthreads();
    }

#pragma unroll
    for (int i = 0; i < 8; i++) {
        int row = m0 + ty * 8 + i;
#pragma unroll
        for (int jq = 0; jq < 2; jq++) {
            int col = n0 + tx * 8 + jq * 4;
            float4 v;
            v.x = acc[i][jq * 4 + 0]; v.y = acc[i][jq * 4 + 1];
            v.z = acc[i][jq * 4 + 2]; v.w = acc[i][jq * 4 + 3];
            if (bias) {
                v.x += bias[col + 0]; v.y += bias[col + 1];
                v.z += bias[col + 2]; v.w += bias[col + 3];
            }
            *(float4*)(out + (size_t)row * N + col) = v;
        }
    }
}

// ---------------------------------------------------------------------------
// Fused attention: per CTA = (b, h, q-tile of 128 rows).
// For each 64-wide K tile: S = (Q/8) K^T ; P = mask ? exp(S) : 0 ;
// den += rowsum(P) ; O += P V.   Final: O/den (0 if den==0).
// Writes context into g_C ([B,S,D] for FC) and res.transpose(1,0,2,3) to out2.
// ---------------------------------------------------------------------------
#define QS_OFF  0
#define KS_OFF  (128*68)
#define VS_OFF  (KS_OFF + 64*68)
#define PS_OFF  (VS_OFF + 64*68)
#define DEN_OFF (PS_OFF + 128*68)
#define ATT_SMEM ((DEN_OFF + 128)*4)

__global__ __launch_bounds__(256, 2)
void attention_kernel(const void* __restrict__ mask, float* __restrict__ resT)
{
    extern __shared__ float sm[];
    float* smQ = sm + QS_OFF;
    float* smK = sm + KS_OFF;
    float* smV = sm + VS_OFF;
    float* smP = sm + PS_OFF;
    float* smD = sm + DEN_OFF;

    const int tid = threadIdx.x;
    const int blk = blockIdx.x;
    const int qt  = blk & 15;          // 16 q-tiles
    const int h   = (blk >> 4) & 15;   // 16 heads
    const int b   = blk >> 8;          // 4 batches
    const int q0  = qt * 128;
    const int mk  = g_mask_kind;

    // Heads are contiguous [S,Dh] slabs of the flat projection output.
    const size_t headBase = (size_t)b * Sq * Dq + (size_t)h * Sq * DHq;
    const float* Qh = g_Q + headBase;
    const float* Kh = g_K + headBase;
    const float* Vh = g_V + headBase;

    // Load Q tile (128 x 64), pre-scaled by 1/sqrt(Dh)=1/8.
#pragma unroll
    for (int l = 0; l < 8; l++) {
        int idx = l * 256 + tid;       // 0..2047 float4s
        int row = idx >> 4;
        int dqo = (idx & 15) * 4;
        float4 v = *(const float4*)(Qh + (size_t)(q0 + row) * DHq + dqo);
        v.x *= 0.125f; v.y *= 0.125f; v.z *= 0.125f; v.w *= 0.125f;
        *(float4*)&smQ[row * 68 + dqo] = v;
    }
    if (tid < 128) smD[tid] = 0.f;

    const int rg = tid >> 3;  // 0..31 -> 4 q-rows each
    const int cg = tid & 7;   // 0..7  -> 8 k-cols each

    float o[4][8];
#pragma unroll
    for (int i = 0; i < 4; i++)
#pragma unroll
        for (int c = 0; c < 8; c++) o[i][c] = 0.f;

    for (int kt = 0; kt < Sq / 64; kt++) {
        const int k0 = kt * 64;
        __syncthreads();   // protects smK/V/P from previous-iter readers
#pragma unroll
        for (int l = 0; l < 4; l++) {
            int idx = l * 256 + tid;   // 0..1023 float4s
            int row = idx >> 4;
            int dqo = (idx & 15) * 4;
            *(float4*)&smK[row * 68 + dqo] =
                *(const float4*)(Kh + (size_t)(k0 + row) * DHq + dqo);
            *(float4*)&smV[row * 68 + dqo] =
                *(const float4*)(Vh + (size_t)(k0 + row) * DHq + dqo);
        }
        __syncthreads();

        // S tile: 4x8 per thread, dot over Dh=64 in float4 chunks.
        float s[4][8];
#pragma unroll
        for (int i = 0; i < 4; i++)
#pragma unroll
            for (int j = 0; j < 8; j++) s[i][j] = 0.f;

#pragma unroll
        for (int dq = 0; dq < 16; dq++) {
            float4 a[4];
#pragma unroll
            for (int i = 0; i < 4; i++)
                a[i] = *(const float4*)&smQ[(rg * 4 + i) * 68 + dq * 4];
#pragma unroll
            for (int jh = 0; jh < 2; jh++) {
                float4 bb[4];
#pragma unroll
                for (int j = 0; j < 4; j++)
                    bb[j] = *(const float4*)&smK[(cg * 8 + jh * 4 + j) * 68 + dq * 4];
#pragma unroll
                for (int i = 0; i < 4; i++)
#pragma unroll
                    for (int j = 0; j < 4; j++)
                        s[i][jh * 4 + j] += a[i].x * bb[j].x + a[i].y * bb[j].y
                                          + a[i].z * bb[j].z + a[i].w * bb[j].w;
            }
        }

        // mask + exp -> P tile in smem
#pragma unroll
        for (int i = 0; i < 4; i++) {
            int qrow = q0 + rg * 4 + i;
            size_t mbase = (size_t)b * Sq * Sq + (size_t)qrow * Sq + k0 + cg * 8;
#pragma unroll
            for (int j = 0; j < 8; j++) {
                bool vis;
                if (mk == 0)      vis = ((const unsigned char*)mask)[mbase + j] != 0;
                else if (mk == 1) vis = ((const int*)mask)[mbase + j] != 0;
                else              vis = ((const float*)mask)[mbase + j] != 0.f;
                smP[(rg * 4 + i) * 68 + cg * 8 + j] = vis ? __expf(s[i][j]) : 0.f;
            }
        }
        __syncthreads();

        // deterministic per-row denominator accumulation
        if (tid < 128) {
            float sum = 0.f;
#pragma unroll
            for (int jq = 0; jq < 16; jq++) {
                float4 v = *(const float4*)&smP[tid * 68 + jq * 4];
                sum += v.x + v.y + v.z + v.w;
            }
            smD[tid] += sum;
        }

        // O += P V
#pragma unroll
        for (int kq = 0; kq < 16; kq++) {
            float4 p[4];
#pragma unroll
            for (int i = 0; i < 4; i++)
                p[i] = *(const float4*)&smP[(rg * 4 + i) * 68 + kq * 4];
            float vb[4][8];
#pragma unroll
            for (int kk = 0; kk < 4; kk++) {
                float4 v0 = *(const float4*)&smV[(kq * 4 + kk) * 68 + cg * 8];
                float4 v1 = *(const float4*)&smV[(kq * 4 + kk) * 68 + cg * 8 + 4];
                vb[kk][0] = v0.x; vb[kk][1] = v0.y; vb[kk][2] = v0.z; vb[kk][3] = v0.w;
                vb[kk][4] = v1.x; vb[kk][5] = v1.y; vb[kk][6] = v1.z; vb[kk][7] = v1.w;
            }
#pragma unroll
            for (int i = 0; i < 4; i++)
#pragma unroll
                for (int c = 0; c < 8; c++)
                    o[i][c] += p[i].x * vb[0][c] + p[i].y * vb[1][c]
                             + p[i].z * vb[2][c] + p[i].w * vb[3][c];
        }
    }
    __syncthreads();

    // Epilogue: normalize (0 if fully masked row), write both outputs.
#pragma unroll
    for (int i = 0; i < 4; i++) {
        int r  = rg * 4 + i;
        float dn  = smD[r];
        float inv = dn > 0.f ? 1.f / dn : 0.f;   // replicates NaN->0
        int s2 = q0 + r;
#pragma unroll
        for (int c4 = 0; c4 < 2; c4++) {
            int c = cg * 8 + c4 * 4;
            float4 v;
            v.x = o[i][c4 * 4 + 0] * inv; v.y = o[i][c4 * 4 + 1] * inv;
            v.z = o[i][c4 * 4 + 2] * inv; v.w = o[i][c4 * 4 + 3] * inv;
            // context for FC: [B, S, H*Dh]
            *(float4*)&g_C[((size_t)b * Sq + s2) * Dq + h * DHq + c] = v;
            // second output: res.transpose(1,0,2,3) = [H, B, S, Dh]
            if (resT)
                *(float4*)&resT[(((size_t)h * Bq + b) * Sq + s2) * DHq + c] = v;
        }
    }
}

// ---------------------------------------------------------------------------
extern "C" void kernel_launch(void* const* d_in, const int* in_sizes, int n_in,
                              void* d_out, int out_size)
{
    const float* query = (const float*)d_in[0];
    const float* key_  = (const float*)d_in[1];
    const float* value = (const float*)d_in[2];
    const void*  mask  = d_in[3];
    const float* Wq    = (const float*)d_in[4];
    const float* Wk    = (const float*)d_in[5];
    const float* Wv    = (const float*)d_in[6];
    const float* fcw   = (const float*)d_in[7];
    const float* fcb   = (const float*)d_in[8];
    float* out = (float*)d_out;

    float *dQ, *dK, *dV, *dC;
    cudaGetSymbolAddress((void**)&dQ, g_Q);
    cudaGetSymbolAddress((void**)&dK, g_K);
    cudaGetSymbolAddress((void**)&dV, g_V);
    cudaGetSymbolAddress((void**)&dC, g_C);

    detect_mask_kernel<<<1, 32>>>((const unsigned char*)mask);

    dim3 gproj(Dq / 128, (Bq * Sq) / 128);   // (8, 64)
    gemm_nt_kernel<<<gproj, 256>>>(query, Wq, nullptr, dQ, Bq * Sq, Dq, Dq);
    gemm_nt_kernel<<<gproj, 256>>>(key_,  Wk, nullptr, dK, Bq * Sq, Dq, Dq);
    gemm_nt_kernel<<<gproj, 256>>>(value, Wv, nullptr, dV, Bq * Sq, Dq, Dq);

    cudaFuncSetAttribute(attention_kernel,
                         cudaFuncAttributeMaxDynamicSharedMemorySize, ATT_SMEM);
    float* resT = (out_size >= 2 * BSDq) ? (out + BSDq) : nullptr;
    attention_kernel<<<Bq * Hq * (Sq / 128), 256, ATT_SMEM>>>(mask, resT);

    gemm_nt_kernel<<<gproj, 256>>>(dC, fcw, fcb, out, Bq * Sq, Dq, Dq);
}

// round 2
// speedup vs baseline: 1.7069x; 1.7069x over previous
#include <cuda_runtime.h>
#include <cuda_bf16.h>
#include <cstdint>
#include <cstddef>

// Problem constants
#define Bq   4
#define Sq   2048
#define Dq   1024
#define Hq   16
#define DHq  64
#define BSDq (Bq*Sq*Dq)   // 8388608

typedef unsigned long long u64;

// packed fp32x2 FMA: d = a*b + d (elementwise on packed pairs), exact fp32 fma.rn
__device__ __forceinline__ void fma2(u64& d, u64 a, u64 b) {
    asm("fma.rn.f32x2 %0, %1, %2, %0;" : "+l"(d) : "l"(a), "l"(b));
}
__device__ __forceinline__ float2 u2f(u64 v) {
    float2 r;
    asm("mov.b64 {%0, %1}, %2;" : "=f"(r.x), "=f"(r.y) : "l"(v));
    return r;
}

// Scratch (device globals: allocation-free rule)
__device__ float g_Q[BSDq];
__device__ float g_K[BSDq];
__device__ float g_V[BSDq];
__device__ float g_C[BSDq];   // context in [B,S,D] layout, input to FC
__device__ int   g_mask_kind; // 0=uint8, 1=int32, 2=float32

// ---------------------------------------------------------------------------
// Mask dtype sniffing (uint8 / int32 / float32 all encode 0/1).
// ---------------------------------------------------------------------------
__global__ void detect_mask_kernel(const unsigned char* __restrict__ m) {
    if (threadIdx.x != 0) return;
    int c0 = 0, c1 = 0, c2 = 0, c3 = 0;
    for (int i = 0; i < 4096; i += 4) {
        if (m[i + 0]) c0++;
        if (m[i + 1]) c1++;
        if (m[i + 2]) c2++;
        if (m[i + 3]) c3++;
    }
    int kind;
    if (c1 == 0 && c2 == 0 && c3 == 0) kind = 1;   // int32: 01 00 00 00
    else if (c0 == 0 && c1 == 0)       kind = 2;   // float32 1.0f: 00 00 80 3F
    else                               kind = 0;   // uint8 bool
    g_mask_kind = kind;
}

// ---------------------------------------------------------------------------
// out[M,N] = X[M,K] @ W[N,K]^T (+bias).  128x128x16 tile, 8x8 per thread,
// packed f32x2 FMAs (pack along N via duplicated-X smem broadcast pairs).
// ---------------------------------------------------------------------------
__global__ __launch_bounds__(256, 2)
void gemm_nt_kernel(const float* __restrict__ X, const float* __restrict__ W,
                    const float* __restrict__ bias, float* __restrict__ out,
                    int M, int N, int K)
{
    __shared__ float Xs[16][264];   // duplicated: Xs[k][2r]=Xs[k][2r+1]=X[m0+r][k]
    __shared__ float Ws[16][132];
    const int tid = threadIdx.x;
    const int tx  = tid & 15;
    const int ty  = tid >> 4;
    const int m0  = blockIdx.y * 128;
    const int n0  = blockIdx.x * 128;

    u64 accp[8][4];
#pragma unroll
    for (int i = 0; i < 8; i++)
#pragma unroll
        for (int j = 0; j < 4; j++) accp[i][j] = 0ull;

    const int lrow0 = (tid) >> 2;           // rows this thread loads
    const int lrow1 = (256 + tid) >> 2;
    const int lkq   = (tid & 3) * 4;

    float4 xr[2], wr[2];
    // load tile 0
    xr[0] = *(const float4*)(X + (size_t)(m0 + lrow0) * K + lkq);
    wr[0] = *(const float4*)(W + (size_t)(n0 + lrow0) * K + lkq);
    xr[1] = *(const float4*)(X + (size_t)(m0 + lrow1) * K + lkq);
    wr[1] = *(const float4*)(W + (size_t)(n0 + lrow1) * K + lkq);

#pragma unroll 1
    for (int k0 = 0; k0 < K; k0 += 16) {
        // store staged regs to smem
#pragma unroll
        for (int l = 0; l < 2; l++) {
            int row = l ? lrow1 : lrow0;
            float4 xv = xr[l], wv = wr[l];
            Xs[lkq + 0][2 * row] = xv.x; Xs[lkq + 0][2 * row + 1] = xv.x;
            Xs[lkq + 1][2 * row] = xv.y; Xs[lkq + 1][2 * row + 1] = xv.y;
            Xs[lkq + 2][2 * row] = xv.z; Xs[lkq + 2][2 * row + 1] = xv.z;
            Xs[lkq + 3][2 * row] = xv.w; Xs[lkq + 3][2 * row + 1] = xv.w;
            Ws[lkq + 0][row] = wv.x; Ws[lkq + 1][row] = wv.y;
            Ws[lkq + 2][row] = wv.z; Ws[lkq + 3][row] = wv.w;
        }
        __syncthreads();

        // prefetch next tile
        if (k0 + 16 < K) {
            xr[0] = *(const float4*)(X + (size_t)(m0 + lrow0) * K + k0 + 16 + lkq);
            wr[0] = *(const float4*)(W + (size_t)(n0 + lrow0) * K + k0 + 16 + lkq);
            xr[1] = *(const float4*)(X + (size_t)(m0 + lrow1) * K + k0 + 16 + lkq);
            wr[1] = *(const float4*)(W + (size_t)(n0 + lrow1) * K + k0 + 16 + lkq);
        }

#pragma unroll
        for (int kk = 0; kk < 16; kk++) {
            ulonglong2 a0 = *(const ulonglong2*)&Xs[kk][ty * 16];
            ulonglong2 a1 = *(const ulonglong2*)&Xs[kk][ty * 16 + 4];
            ulonglong2 a2 = *(const ulonglong2*)&Xs[kk][ty * 16 + 8];
            ulonglong2 a3 = *(const ulonglong2*)&Xs[kk][ty * 16 + 12];
            ulonglong2 b0 = *(const ulonglong2*)&Ws[kk][tx * 8];
            ulonglong2 b1 = *(const ulonglong2*)&Ws[kk][tx * 8 + 4];
            u64 ar[8] = {a0.x, a0.y, a1.x, a1.y, a2.x, a2.y, a3.x, a3.y};
            u64 br[4] = {b0.x, b0.y, b1.x, b1.y};
#pragma unroll
            for (int i = 0; i < 8; i++)
#pragma unroll
                for (int j = 0; j < 4; j++)
                    fma2(accp[i][j], ar[i], br[j]);
        }
        __syncthreads();
    }

#pragma unroll
    for (int i = 0; i < 8; i++) {
        int row = m0 + ty * 8 + i;
#pragma unroll
        for (int j = 0; j < 4; j++) {
            int col = n0 + tx * 8 + 2 * j;
            float2 c = u2f(accp[i][j]);
            if (bias) { c.x += bias[col]; c.y += bias[col + 1]; }
            *(float2*)(out + (size_t)row * N + col) = c;
        }
    }
}

// ---------------------------------------------------------------------------
// Fused attention, packed f32x2 everywhere (pack over the reduction dim).
// CTA = (b, h, 128 q-rows). Per 64-wide k-tile:
//   S = (Q/8) K^T (pairs over dh) ; P = mask ? exp(S) : 0 ; den += rowsum(P);
//   O += P V (pairs over k, V held transposed in smem).
// Thread tile: 4 q-rows (rg) x 8 k-cols {cg+8t} -> conflict-free smem walks.
// ---------------------------------------------------------------------------
#define ATT_SMEM ((68*(128+64+64+128) + 128)*4)

__global__ __launch_bounds__(256, 1)
void attention_kernel(const void* __restrict__ mask, float* __restrict__ resT)
{
    extern __shared__ float sm[];
    float* smQ  = sm;                   // 128 x 68
    float* smK  = smQ  + 128 * 68;      // 64 x 68  (row-major over dh)
    float* smVt = smK  + 64 * 68;       // 64 x 68  (TRANSPOSED: [c][k])
    float* smP  = smVt + 64 * 68;       // 128 x 68
    float* smD  = smP  + 128 * 68;      // 128

    const int tid = threadIdx.x;
    const int blk = blockIdx.x;
    const int qt  = blk & 15;
    const int h   = (blk >> 4) & 15;
    const int b   = blk >> 8;
    const int q0  = qt * 128;
    const int mk  = g_mask_kind;

    const size_t headBase = (size_t)b * Sq * Dq + (size_t)h * Sq * DHq;
    const float* Qh = g_Q + headBase;
    const float* Kh = g_K + headBase;
    const float* Vh = g_V + headBase;

    // Q tile (128x64), pre-scaled by 1/8
#pragma unroll
    for (int l = 0; l < 8; l++) {
        int idx = l * 256 + tid;
        int row = idx >> 4;
        int dqo = (idx & 15) * 4;
        float4 v = *(const float4*)(Qh + (size_t)(q0 + row) * DHq + dqo);
        v.x *= 0.125f; v.y *= 0.125f; v.z *= 0.125f; v.w *= 0.125f;
        *(float4*)&smQ[row * 68 + dqo] = v;
    }
    if (tid < 128) smD[tid] = 0.f;

    // K/V tile 0 -> smem (V transposed; V loaded with k varying across lanes
    // so the transpose STS is bank-conflict-free)
#pragma unroll
    for (int l = 0; l < 4; l++) {
        int idx  = l * 256 + tid;
        int krow = idx >> 4, kc = (idx & 15) * 4;
        *(float4*)&smK[krow * 68 + kc] =
            *(const float4*)(Kh + (size_t)krow * DHq + kc);
        int vk = idx & 63, vc = (idx >> 6) * 4;
        float4 vv = *(const float4*)(Vh + (size_t)vk * DHq + vc);
        smVt[(vc + 0) * 68 + vk] = vv.x;
        smVt[(vc + 1) * 68 + vk] = vv.y;
        smVt[(vc + 2) * 68 + vk] = vv.z;
        smVt[(vc + 3) * 68 + vk] = vv.w;
    }
    __syncthreads();

    const int rg = tid >> 3;  // 0..31 -> 4 q-rows each
    const int cg = tid & 7;   // cols cg, cg+8, ..., cg+56

    u64 o2[4][8];
#pragma unroll
    for (int i = 0; i < 4; i++)
#pragma unroll
        for (int t = 0; t < 8; t++) o2[i][t] = 0ull;

#pragma unroll 1
    for (int kt = 0; kt < Sq / 64; kt++) {
        // prefetch next K/V tile into regs (hidden under QK compute)
        float4 kr[4], vr[4];
        const bool have = (kt + 1 < Sq / 64);
        if (have) {
            const float* Kn = Kh + (size_t)(kt + 1) * 64 * DHq;
            const float* Vn = Vh + (size_t)(kt + 1) * 64 * DHq;
#pragma unroll
            for (int l = 0; l < 4; l++) {
                int idx = l * 256 + tid;
                kr[l] = *(const float4*)(Kn + (size_t)(idx >> 4) * DHq + (idx & 15) * 4);
                vr[l] = *(const float4*)(Vn + (size_t)(idx & 63) * DHq + ((idx >> 6) * 4));
            }
        }

        // ---- S = Q K^T, packed over dh ----
        u64 s2[4][8];
#pragma unroll
        for (int i = 0; i < 4; i++)
#pragma unroll
            for (int t = 0; t < 8; t++) s2[i][t] = 0ull;

#pragma unroll
        for (int q = 0; q < 16; q++) {
            ulonglong2 a[4];
#pragma unroll
            for (int i = 0; i < 4; i++)
                a[i] = *(const ulonglong2*)&smQ[(rg * 4 + i) * 68 + q * 4];
#pragma unroll
            for (int t = 0; t < 8; t++) {
                ulonglong2 kk = *(const ulonglong2*)&smK[(cg + 8 * t) * 68 + q * 4];
#pragma unroll
                for (int i = 0; i < 4; i++) {
                    fma2(s2[i][t], a[i].x, kk.x);
                    fma2(s2[i][t], a[i].y, kk.y);
                }
            }
        }

        // ---- mask + exp -> P ----
        const int k0 = kt * 64;
#pragma unroll
        for (int i = 0; i < 4; i++) {
            int qrow = q0 + rg * 4 + i;
            size_t mbase = (size_t)b * Sq * Sq + (size_t)qrow * Sq + k0 + cg;
            float* prow = &smP[(rg * 4 + i) * 68 + cg];
#pragma unroll
            for (int t = 0; t < 8; t++) {
                float2 sp = u2f(s2[i][t]);
                float sv = sp.x + sp.y;
                bool vis;
                if (mk == 0)      vis = ((const unsigned char*)mask)[mbase + 8 * t] != 0;
                else if (mk == 1) vis = ((const int*)mask)[mbase + 8 * t] != 0;
                else              vis = ((const float*)mask)[mbase + 8 * t] != 0.f;
                prow[8 * t] = vis ? __expf(sv) : 0.f;
            }
        }
        __syncthreads();

        // ---- deterministic per-row denominator ----
        if (tid < 128) {
            float ssum = 0.f;
#pragma unroll
            for (int jq = 0; jq < 16; jq++) {
                float4 v = *(const float4*)&smP[tid * 68 + jq * 4];
                ssum += v.x + v.y + v.z + v.w;
            }
            smD[tid] += ssum;
        }

        // ---- O += P V, packed over k (V transposed in smem) ----
#pragma unroll
        for (int q = 0; q < 16; q++) {
            ulonglong2 pp[4];
#pragma unroll
            for (int i = 0; i < 4; i++)
                pp[i] = *(const ulonglong2*)&smP[(rg * 4 + i) * 68 + q * 4];
#pragma unroll
            for (int t = 0; t < 8; t++) {
                ulonglong2 vv = *(const ulonglong2*)&smVt[(cg + 8 * t) * 68 + q * 4];
#pragma unroll
                for (int i = 0; i < 4; i++) {
                    fma2(o2[i][t], pp[i].x, vv.x);
                    fma2(o2[i][t], pp[i].y, vv.y);
                }
            }
        }
        __syncthreads();

        // commit prefetched tile to smem
        if (have) {
#pragma unroll
            for (int l = 0; l < 4; l++) {
                int idx = l * 256 + tid;
                *(float4*)&smK[(idx >> 4) * 68 + (idx & 15) * 4] = kr[l];
                int vk = idx & 63, vc = (idx >> 6) * 4;
                smVt[(vc + 0) * 68 + vk] = vr[l].x;
                smVt[(vc + 1) * 68 + vk] = vr[l].y;
                smVt[(vc + 2) * 68 + vk] = vr[l].z;
                smVt[(vc + 3) * 68 + vk] = vr[l].w;
            }
            __syncthreads();
        }
    }

    // ---- epilogue: normalize (0 if fully-masked row), write both outputs ----
#pragma unroll
    for (int i = 0; i < 4; i++) {
        int r = rg * 4 + i;
        float dn  = smD[r];
        float inv = dn > 0.f ? 1.f / dn : 0.f;   // replicates NaN->0
        int s2r = q0 + r;
#pragma unroll
        for (int t = 0; t < 8; t++) {
            float2 ov = u2f(o2[i][t]);
            float val = (ov.x + ov.y) * inv;
            int c = cg + 8 * t;
            g_C[((size_t)b * Sq + s2r) * Dq + h * DHq + c] = val;
            if (resT)
                resT[(((size_t)h * Bq + b) * Sq + s2r) * DHq + c] = val;
        }
    }
}

// ---------------------------------------------------------------------------
extern "C" void kernel_launch(void* const* d_in, const int* in_sizes, int n_in,
                              void* d_out, int out_size)
{
    const float* query = (const float*)d_in[0];
    const float* key_  = (const float*)d_in[1];
    const float* value = (const float*)d_in[2];
    const void*  mask  = d_in[3];
    const float* Wq    = (const float*)d_in[4];
    const float* Wk    = (const float*)d_in[5];
    const float* Wv    = (const float*)d_in[6];
    const float* fcw   = (const float*)d_in[7];
    const float* fcb   = (const float*)d_in[8];
    float* out = (float*)d_out;

    float *dQ, *dK, *dV, *dC;
    cudaGetSymbolAddress((void**)&dQ, g_Q);
    cudaGetSymbolAddress((void**)&dK, g_K);
    cudaGetSymbolAddress((void**)&dV, g_V);
    cudaGetSymbolAddress((void**)&dC, g_C);

    detect_mask_kernel<<<1, 32>>>((const unsigned char*)mask);

    dim3 gproj(Dq / 128, (Bq * Sq) / 128);   // (8, 64)
    gemm_nt_kernel<<<gproj, 256>>>(query, Wq, nullptr, dQ, Bq * Sq, Dq, Dq);
    gemm_nt_kernel<<<gproj, 256>>>(key_,  Wk, nullptr, dK, Bq * Sq, Dq, Dq);
    gemm_nt_kernel<<<gproj, 256>>>(value, Wv, nullptr, dV, Bq * Sq, Dq, Dq);

    cudaFuncSetAttribute(attention_kernel,
                         cudaFuncAttributeMaxDynamicSharedMemorySize, ATT_SMEM);
    float* resT = (out_size >= 2 * BSDq) ? (out + BSDq) : nullptr;
    attention_kernel<<<Bq * Hq * (Sq / 128), 256, ATT_SMEM>>>(mask, resT);

    gemm_nt_kernel<<<gproj, 256>>>(dC, fcw, fcb, out, Bq * Sq, Dq, Dq);
}

// round 3
// speedup vs baseline: 1.9648x; 1.1511x over previous
#include <cuda_runtime.h>
#include <cuda_bf16.h>
#include <cstdint>
#include <cstddef>

// Problem constants
#define Bq   4
#define Sq   2048
#define Dq   1024
#define Hq   16
#define DHq  64
#define BSDq (Bq*Sq*Dq)   // 8388608

typedef unsigned long long u64;

// packed fp32x2 FMA: d = a*b + d (elementwise on packed pairs), exact fp32 fma.rn
__device__ __forceinline__ void fma2(u64& d, u64 a, u64 b) {
    asm("fma.rn.f32x2 %0, %1, %2, %0;" : "+l"(d) : "l"(a), "l"(b));
}
__device__ __forceinline__ float2 u2f(u64 v) {
    float2 r;
    asm("mov.b64 {%0, %1}, %2;" : "=f"(r.x), "=f"(r.y) : "l"(v));
    return r;
}
__device__ __forceinline__ u64 dup2(float x) {
    u64 r;
    asm("mov.b64 %0, {%1, %1};" : "=l"(r) : "f"(x));
    return r;
}

// Scratch (device globals: allocation-free rule)
__device__ float g_Q[BSDq];
__device__ float g_K[BSDq];
__device__ float g_V[BSDq];
__device__ float g_C[BSDq];   // context in [B,S,D] layout, input to FC
__device__ int   g_mask_kind; // 0=uint8, 1=int32, 2=float32

// ---------------------------------------------------------------------------
// Mask dtype sniffing (uint8 / int32 / float32 all encode 0/1).
// ---------------------------------------------------------------------------
__global__ void detect_mask_kernel(const unsigned char* __restrict__ m) {
    if (threadIdx.x != 0) return;
    int c0 = 0, c1 = 0, c2 = 0, c3 = 0;
    for (int i = 0; i < 4096; i += 4) {
        if (m[i + 0]) c0++;
        if (m[i + 1]) c1++;
        if (m[i + 2]) c2++;
        if (m[i + 3]) c3++;
    }
    int kind;
    if (c1 == 0 && c2 == 0 && c3 == 0) kind = 1;   // int32: 01 00 00 00
    else if (c0 == 0 && c1 == 0)       kind = 2;   // float32 1.0f: 00 00 80 3F
    else                               kind = 0;   // uint8 bool
    g_mask_kind = kind;
}

// ---------------------------------------------------------------------------
// out[M,N] = X[M,K] @ W[N,K]^T (+bias).  128x128x16 tile, 8x8 per thread.
// Packed f32x2 FMAs, pairs over M (natural ulonglong2 from Xs[k][row]);
// W scalars duplicated into pairs via register mov.b64 (alu pipe, free).
// Per kk/thread: 4 LDS.128 + 8 MOV + 32 FFMA2 -> balanced at FFMA2 floor.
// ---------------------------------------------------------------------------
__global__ __launch_bounds__(256, 2)
void gemm_nt_kernel(const float* __restrict__ X, const float* __restrict__ W,
                    const float* __restrict__ bias, float* __restrict__ out,
                    int M, int N, int K)
{
    __shared__ float Xs[16][132];
    __shared__ float Ws[16][132];
    const int tid = threadIdx.x;
    const int tx  = tid & 15;
    const int ty  = tid >> 4;
    const int m0  = blockIdx.y * 128;
    const int n0  = blockIdx.x * 128;

    // acc[ip][j]: M-pair ip covers rows (ty*8+2ip, ty*8+2ip+1), col tx*8+j
    u64 accp[4][8];
#pragma unroll
    for (int i = 0; i < 4; i++)
#pragma unroll
        for (int j = 0; j < 8; j++) accp[i][j] = 0ull;

    const int lrow0 = (tid) >> 2;
    const int lrow1 = (256 + tid) >> 2;
    const int lkq   = (tid & 3) * 4;

    float4 xr[2], wr[2];
    xr[0] = *(const float4*)(X + (size_t)(m0 + lrow0) * K + lkq);
    wr[0] = *(const float4*)(W + (size_t)(n0 + lrow0) * K + lkq);
    xr[1] = *(const float4*)(X + (size_t)(m0 + lrow1) * K + lkq);
    wr[1] = *(const float4*)(W + (size_t)(n0 + lrow1) * K + lkq);

#pragma unroll 1
    for (int k0 = 0; k0 < K; k0 += 16) {
#pragma unroll
        for (int l = 0; l < 2; l++) {
            int row = l ? lrow1 : lrow0;
            float4 xv = xr[l], wv = wr[l];
            Xs[lkq + 0][row] = xv.x; Xs[lkq + 1][row] = xv.y;
            Xs[lkq + 2][row] = xv.z; Xs[lkq + 3][row] = xv.w;
            Ws[lkq + 0][row] = wv.x; Ws[lkq + 1][row] = wv.y;
            Ws[lkq + 2][row] = wv.z; Ws[lkq + 3][row] = wv.w;
        }
        __syncthreads();

        if (k0 + 16 < K) {
            xr[0] = *(const float4*)(X + (size_t)(m0 + lrow0) * K + k0 + 16 + lkq);
            wr[0] = *(const float4*)(W + (size_t)(n0 + lrow0) * K + k0 + 16 + lkq);
            xr[1] = *(const float4*)(X + (size_t)(m0 + lrow1) * K + k0 + 16 + lkq);
            wr[1] = *(const float4*)(W + (size_t)(n0 + lrow1) * K + k0 + 16 + lkq);
        }

#pragma unroll
        for (int kk = 0; kk < 16; kk++) {
            // a: 4 natural M-pairs (rows ty*8 .. ty*8+7)
            ulonglong2 a01 = *(const ulonglong2*)&Xs[kk][ty * 8];
            ulonglong2 a23 = *(const ulonglong2*)&Xs[kk][ty * 8 + 4];
            u64 ap[4] = {a01.x, a01.y, a23.x, a23.y};
            // b: 8 W scalars, duplicated into pairs in registers
            float4 w0 = *(const float4*)&Ws[kk][tx * 8];
            float4 w1 = *(const float4*)&Ws[kk][tx * 8 + 4];
            u64 bp[8];
            bp[0] = dup2(w0.x); bp[1] = dup2(w0.y);
            bp[2] = dup2(w0.z); bp[3] = dup2(w0.w);
            bp[4] = dup2(w1.x); bp[5] = dup2(w1.y);
            bp[6] = dup2(w1.z); bp[7] = dup2(w1.w);
#pragma unroll
            for (int i = 0; i < 4; i++)
#pragma unroll
                for (int j = 0; j < 8; j++)
                    fma2(accp[i][j], ap[i], bp[j]);
        }
        __syncthreads();
    }

    // Epilogue: each M-pair ip gives two full 8-col rows for this thread.
#pragma unroll
    for (int ip = 0; ip < 4; ip++) {
        int row0 = m0 + ty * 8 + 2 * ip;
        float r0v[8], r1v[8];
#pragma unroll
        for (int j = 0; j < 8; j++) {
            float2 c = u2f(accp[ip][j]);
            r0v[j] = c.x; r1v[j] = c.y;
        }
        if (bias) {
#pragma unroll
            for (int j = 0; j < 8; j++) {
                float bv = bias[n0 + tx * 8 + j];
                r0v[j] += bv; r1v[j] += bv;
            }
        }
        int colb = n0 + tx * 8;
        *(float4*)(out + (size_t)row0 * N + colb)           = *(float4*)&r0v[0];
        *(float4*)(out + (size_t)row0 * N + colb + 4)       = *(float4*)&r0v[4];
        *(float4*)(out + (size_t)(row0 + 1) * N + colb)     = *(float4*)&r1v[0];
        *(float4*)(out + (size_t)(row0 + 1) * N + colb + 4) = *(float4*)&r1v[4];
    }
}

// ---------------------------------------------------------------------------
// Fused attention, packed f32x2 (pack over the reduction dim). Unchanged
// from R2 (matched prediction there; LDS-bound fix is next round's target).
// ---------------------------------------------------------------------------
#define ATT_SMEM ((68*(128+64+64+128) + 128)*4)

__global__ __launch_bounds__(256, 1)
void attention_kernel(const void* __restrict__ mask, float* __restrict__ resT)
{
    extern __shared__ float sm[];
    float* smQ  = sm;                   // 128 x 68
    float* smK  = smQ  + 128 * 68;      // 64 x 68  (row-major over dh)
    float* smVt = smK  + 64 * 68;       // 64 x 68  (TRANSPOSED: [c][k])
    float* smP  = smVt + 64 * 68;       // 128 x 68
    float* smD  = smP  + 128 * 68;      // 128

    const int tid = threadIdx.x;
    const int blk = blockIdx.x;
    const int qt  = blk & 15;
    const int h   = (blk >> 4) & 15;
    const int b   = blk >> 8;
    const int q0  = qt * 128;
    const int mk  = g_mask_kind;

    const size_t headBase = (size_t)b * Sq * Dq + (size_t)h * Sq * DHq;
    const float* Qh = g_Q + headBase;
    const float* Kh = g_K + headBase;
    const float* Vh = g_V + headBase;

#pragma unroll
    for (int l = 0; l < 8; l++) {
        int idx = l * 256 + tid;
        int row = idx >> 4;
        int dqo = (idx & 15) * 4;
        float4 v = *(const float4*)(Qh + (size_t)(q0 + row) * DHq + dqo);
        v.x *= 0.125f; v.y *= 0.125f; v.z *= 0.125f; v.w *= 0.125f;
        *(float4*)&smQ[row * 68 + dqo] = v;
    }
    if (tid < 128) smD[tid] = 0.f;

#pragma unroll
    for (int l = 0; l < 4; l++) {
        int idx  = l * 256 + tid;
        int krow = idx >> 4, kc = (idx & 15) * 4;
        *(float4*)&smK[krow * 68 + kc] =
            *(const float4*)(Kh + (size_t)krow * DHq + kc);
        int vk = idx & 63, vc = (idx >> 6) * 4;
        float4 vv = *(const float4*)(Vh + (size_t)vk * DHq + vc);
        smVt[(vc + 0) * 68 + vk] = vv.x;
        smVt[(vc + 1) * 68 + vk] = vv.y;
        smVt[(vc + 2) * 68 + vk] = vv.z;
        smVt[(vc + 3) * 68 + vk] = vv.w;
    }
    __syncthreads();

    const int rg = tid >> 3;
    const int cg = tid & 7;

    u64 o2[4][8];
#pragma unroll
    for (int i = 0; i < 4; i++)
#pragma unroll
        for (int t = 0; t < 8; t++) o2[i][t] = 0ull;

#pragma unroll 1
    for (int kt = 0; kt < Sq / 64; kt++) {
        float4 kr[4], vr[4];
        const bool have = (kt + 1 < Sq / 64);
        if (have) {
            const float* Kn = Kh + (size_t)(kt + 1) * 64 * DHq;
            const float* Vn = Vh + (size_t)(kt + 1) * 64 * DHq;
#pragma unroll
            for (int l = 0; l < 4; l++) {
                int idx = l * 256 + tid;
                kr[l] = *(const float4*)(Kn + (size_t)(idx >> 4) * DHq + (idx & 15) * 4);
                vr[l] = *(const float4*)(Vn + (size_t)(idx & 63) * DHq + ((idx >> 6) * 4));
            }
        }

        u64 s2[4][8];
#pragma unroll
        for (int i = 0; i < 4; i++)
#pragma unroll
            for (int t = 0; t < 8; t++) s2[i][t] = 0ull;

#pragma unroll
        for (int q = 0; q < 16; q++) {
            ulonglong2 a[4];
#pragma unroll
            for (int i = 0; i < 4; i++)
                a[i] = *(const ulonglong2*)&smQ[(rg * 4 + i) * 68 + q * 4];
#pragma unroll
            for (int t = 0; t < 8; t++) {
                ulonglong2 kk = *(const ulonglong2*)&smK[(cg + 8 * t) * 68 + q * 4];
#pragma unroll
                for (int i = 0; i < 4; i++) {
                    fma2(s2[i][t], a[i].x, kk.x);
                    fma2(s2[i][t], a[i].y, kk.y);
                }
            }
        }

        const int k0 = kt * 64;
#pragma unroll
        for (int i = 0; i < 4; i++) {
            int qrow = q0 + rg * 4 + i;
            size_t mbase = (size_t)b * Sq * Sq + (size_t)qrow * Sq + k0 + cg;
            float* prow = &smP[(rg * 4 + i) * 68 + cg];
#pragma unroll
            for (int t = 0; t < 8; t++) {
                float2 sp = u2f(s2[i][t]);
                float sv = sp.x + sp.y;
                bool vis;
                if (mk == 0)      vis = ((const unsigned char*)mask)[mbase + 8 * t] != 0;
                else if (mk == 1) vis = ((const int*)mask)[mbase + 8 * t] != 0;
                else              vis = ((const float*)mask)[mbase + 8 * t] != 0.f;
                prow[8 * t] = vis ? __expf(sv) : 0.f;
            }
        }
        __syncthreads();

        if (tid < 128) {
            float ssum = 0.f;
#pragma unroll
            for (int jq = 0; jq < 16; jq++) {
                float4 v = *(const float4*)&smP[tid * 68 + jq * 4];
                ssum += v.x + v.y + v.z + v.w;
            }
            smD[tid] += ssum;
        }

#pragma unroll
        for (int q = 0; q < 16; q++) {
            ulonglong2 pp[4];
#pragma unroll
            for (int i = 0; i < 4; i++)
                pp[i] = *(const ulonglong2*)&smP[(rg * 4 + i) * 68 + q * 4];
#pragma unroll
            for (int t = 0; t < 8; t++) {
                ulonglong2 vv = *(const ulonglong2*)&smVt[(cg + 8 * t) * 68 + q * 4];
#pragma unroll
                for (int i = 0; i < 4; i++) {
                    fma2(o2[i][t], pp[i].x, vv.x);
                    fma2(o2[i][t], pp[i].y, vv.y);
                }
            }
        }
        __syncthreads();

        if (have) {
#pragma unroll
            for (int l = 0; l < 4; l++) {
                int idx = l * 256 + tid;
                *(float4*)&smK[(idx >> 4) * 68 + (idx & 15) * 4] = kr[l];
                int vk = idx & 63, vc = (idx >> 6) * 4;
                smVt[(vc + 0) * 68 + vk] = vr[l].x;
                smVt[(vc + 1) * 68 + vk] = vr[l].y;
                smVt[(vc + 2) * 68 + vk] = vr[l].z;
                smVt[(vc + 3) * 68 + vk] = vr[l].w;
            }
            __syncthreads();
        }
    }

#pragma unroll
    for (int i = 0; i < 4; i++) {
        int r = rg * 4 + i;
        float dn  = smD[r];
        float inv = dn > 0.f ? 1.f / dn : 0.f;
        int s2r = q0 + r;
#pragma unroll
        for (int t = 0; t < 8; t++) {
            float2 ov = u2f(o2[i][t]);
            float val = (ov.x + ov.y) * inv;
            int c = cg + 8 * t;
            g_C[((size_t)b * Sq + s2r) * Dq + h * DHq + c] = val;
            if (resT)
                resT[(((size_t)h * Bq + b) * Sq + s2r) * DHq + c] = val;
        }
    }
}

// ---------------------------------------------------------------------------
extern "C" void kernel_launch(void* const* d_in, const int* in_sizes, int n_in,
                              void* d_out, int out_size)
{
    const float* query = (const float*)d_in[0];
    const float* key_  = (const float*)d_in[1];
    const float* value = (const float*)d_in[2];
    const void*  mask  = d_in[3];
    const float* Wq    = (const float*)d_in[4];
    const float* Wk    = (const float*)d_in[5];
    const float* Wv    = (const float*)d_in[6];
    const float* fcw   = (const float*)d_in[7];
    const float* fcb   = (const float*)d_in[8];
    float* out = (float*)d_out;

    float *dQ, *dK, *dV, *dC;
    cudaGetSymbolAddress((void**)&dQ, g_Q);
    cudaGetSymbolAddress((void**)&dK, g_K);
    cudaGetSymbolAddress((void**)&dV, g_V);
    cudaGetSymbolAddress((void**)&dC, g_C);

    detect_mask_kernel<<<1, 32>>>((const unsigned char*)mask);

    dim3 gproj(Dq / 128, (Bq * Sq) / 128);   // (8, 64)
    gemm_nt_kernel<<<gproj, 256>>>(query, Wq, nullptr, dQ, Bq * Sq, Dq, Dq);
    gemm_nt_kernel<<<gproj, 256>>>(key_,  Wk, nullptr, dK, Bq * Sq, Dq, Dq);
    gemm_nt_kernel<<<gproj, 256>>>(value, Wv, nullptr, dV, Bq * Sq, Dq, Dq);

    cudaFuncSetAttribute(attention_kernel,
                         cudaFuncAttributeMaxDynamicSharedMemorySize, ATT_SMEM);
    float* resT = (out_size >= 2 * BSDq) ? (out + BSDq) : nullptr;
    attention_kernel<<<Bq * Hq * (Sq / 128), 256, ATT_SMEM>>>(mask, resT);

    gemm_nt_kernel<<<gproj, 256>>>(dC, fcw, fcb, out, Bq * Sq, Dq, Dq);
}

// round 5
// speedup vs baseline: 2.6231x; 1.3350x over previous
#include <cuda_runtime.h>
#include <cuda_bf16.h>
#include <cstdint>
#include <cstddef>

// Problem constants
#define Bq   4
#define Sq   2048
#define Dq   1024
#define Hq   16
#define DHq  64
#define BSDq (Bq*Sq*Dq)   // 8388608

typedef unsigned long long u64;

// ---------------- packed fp32x2 helpers (attention kernel) -----------------
__device__ __forceinline__ void fma2(u64& d, u64 a, u64 b) {
    asm("fma.rn.f32x2 %0, %1, %2, %0;" : "+l"(d) : "l"(a), "l"(b));
}
__device__ __forceinline__ float2 u2f(u64 v) {
    float2 r;
    asm("mov.b64 {%0, %1}, %2;" : "=f"(r.x), "=f"(r.y) : "l"(v));
    return r;
}

// ---------------- generic-PTX tensor-core helpers (sm_80+ ISA) -------------
__device__ __forceinline__ uint32_t smem_u32(const void* p) {
    uint32_t a;
    asm("{ .reg .u64 t; cvta.to.shared.u64 t, %1; cvt.u32.u64 %0, t; }"
        : "=r"(a) : "l"(p));
    return a;
}
__device__ __forceinline__ void cp_async16(uint32_t s, const void* g) {
    asm volatile("cp.async.cg.shared.global [%0], [%1], 16;" :: "r"(s), "l"(g));
}
#define CP_COMMIT() asm volatile("cp.async.commit_group;" ::: "memory")
#define CP_WAIT(n)  asm volatile("cp.async.wait_group %0;" :: "n"(n) : "memory")

__device__ __forceinline__ void ldsm4(uint32_t* r, uint32_t addr) {
    asm volatile("ldmatrix.sync.aligned.m8n8.x4.shared.b16 {%0,%1,%2,%3}, [%4];"
                 : "=r"(r[0]), "=r"(r[1]), "=r"(r[2]), "=r"(r[3]) : "r"(addr));
}
// D(f32) += A(bf16) * B(bf16); m16n8k16 row.col
__device__ __forceinline__ void mma16816(float* d, const uint32_t* a,
                                         uint32_t b0, uint32_t b1) {
    asm volatile(
        "mma.sync.aligned.m16n8k16.row.col.f32.bf16.bf16.f32 "
        "{%0,%1,%2,%3}, {%4,%5,%6,%7}, {%8,%9}, {%0,%1,%2,%3};"
        : "+f"(d[0]), "+f"(d[1]), "+f"(d[2]), "+f"(d[3])
        : "r"(a[0]), "r"(a[1]), "r"(a[2]), "r"(a[3]), "r"(b0), "r"(b1));
}
// byte offset of (row, 16B-chunk) in a [rows][64 bf16] tile, SW128-style xor
__device__ __forceinline__ uint32_t swz(int row, int ch) {
    uint32_t off = (uint32_t)(row * 128 + ch * 16);
    return off ^ (((uint32_t)row & 7u) << 4);
}

// ---------------- scratch (device globals: allocation-free rule) -----------
__device__ float g_Q[BSDq];
__device__ float g_K[BSDq];
__device__ float g_V[BSDq];
__device__ float g_C[BSDq];
__device__ int   g_mask_kind;
__device__ __align__(16) __nv_bfloat16 g_xhi[BSDq];
__device__ __align__(16) __nv_bfloat16 g_xlo[BSDq];
__device__ __align__(16) __nv_bfloat16 g_whi[Dq * Dq];
__device__ __align__(16) __nv_bfloat16 g_wlo[Dq * Dq];

// ---------------------------------------------------------------------------
__global__ void detect_mask_kernel(const unsigned char* __restrict__ m) {
    if (threadIdx.x != 0) return;
    int c0 = 0, c1 = 0, c2 = 0, c3 = 0;
    for (int i = 0; i < 4096; i += 4) {
        if (m[i + 0]) c0++;
        if (m[i + 1]) c1++;
        if (m[i + 2]) c2++;
        if (m[i + 3]) c3++;
    }
    int kind;
    if (c1 == 0 && c2 == 0 && c3 == 0) kind = 1;
    else if (c0 == 0 && c1 == 0)       kind = 2;
    else                               kind = 0;
    g_mask_kind = kind;
}

// fp32 -> bf16 hi/lo split (hi = rn(x), lo = rn(x - hi))
__global__ __launch_bounds__(256)
void split_kernel(const float* __restrict__ x, __nv_bfloat16* __restrict__ hi,
                  __nv_bfloat16* __restrict__ lo, int n)
{
    int i = (blockIdx.x * 256 + threadIdx.x) * 4;
    if (i >= n) return;
    float4 v = *(const float4*)(x + i);
    __nv_bfloat16 h0 = __float2bfloat16(v.x), h1 = __float2bfloat16(v.y);
    __nv_bfloat16 h2 = __float2bfloat16(v.z), h3 = __float2bfloat16(v.w);
    __nv_bfloat162 hA, hB, lA, lB;
    hA.x = h0; hA.y = h1; hB.x = h2; hB.y = h3;
    lA.x = __float2bfloat16(v.x - __bfloat162float(h0));
    lA.y = __float2bfloat16(v.y - __bfloat162float(h1));
    lB.x = __float2bfloat16(v.z - __bfloat162float(h2));
    lB.y = __float2bfloat16(v.w - __bfloat162float(h3));
    *(__nv_bfloat162*)(hi + i)     = hA;
    *(__nv_bfloat162*)(hi + i + 2) = hB;
    *(__nv_bfloat162*)(lo + i)     = lA;
    *(__nv_bfloat162*)(lo + i + 2) = lB;
}

// ---------------------------------------------------------------------------
// Tensor-core (HMMA via mma.sync) split-bf16 GEMM:
// out[M,N] = X @ W^T (+bias) with fp32-level accuracy via
// Ahi*Bhi + Ahi*Blo + Alo*Bhi.  CTA = 128x128 tile, 8 warps of 64x32,
// K in 64-chunks, cp.async double-buffered smem, swizzled ldmatrix loads.
// ---------------------------------------------------------------------------
#define GSTAGE  65536        // 4 matrices x 128x64 bf16 (16KB each)
#define GA_HI   0
#define GA_LO   16384
#define GB_HI   32768
#define GB_LO   49152
#define GSMEM   (2*GSTAGE)   // 128KB

__global__ __launch_bounds__(256, 1)
void gemm_tc_kernel(const __nv_bfloat16* __restrict__ Ahi,
                    const __nv_bfloat16* __restrict__ Alo,
                    const __nv_bfloat16* __restrict__ Bhi,
                    const __nv_bfloat16* __restrict__ Blo,
                    const float* __restrict__ bias, float* __restrict__ out,
                    int M, int N, int K)
{
    extern __shared__ char smem[];
    const uint32_t sbase = smem_u32(smem);
    const int tid  = threadIdx.x;
    const int wid  = tid >> 5;
    const int lane = tid & 31;
    const int m0 = blockIdx.y * 128;
    const int n0 = blockIdx.x * 128;
    const int wm = wid & 1;        // 2 m-warps (64 rows each)
    const int wn = wid >> 1;       // 4 n-warps (32 cols each)

    float acc[4][4][4];
#pragma unroll
    for (int i = 0; i < 4; i++)
#pragma unroll
        for (int j = 0; j < 4; j++)
#pragma unroll
            for (int c = 0; c < 4; c++) acc[i][j][c] = 0.f;

    // stage-load slots: idx = l*256+tid -> row = idx>>3 (0..127), ch = idx&7
    int lrow[4], lch[4];
#pragma unroll
    for (int l = 0; l < 4; l++) {
        int idx = l * 256 + tid;
        lrow[l] = idx >> 3;
        lch[l]  = idx & 7;
    }

    auto load_stage = [&](int t, int buf) {
        const int k0 = t * 64;
        const uint32_t sb = sbase + buf * GSTAGE;
#pragma unroll
        for (int l = 0; l < 4; l++) {
            uint32_t sw = swz(lrow[l], lch[l]);
            size_t ao = (size_t)(m0 + lrow[l]) * K + k0 + lch[l] * 8;
            size_t bo = (size_t)(n0 + lrow[l]) * K + k0 + lch[l] * 8;
            cp_async16(sb + GA_HI + sw, Ahi + ao);
            cp_async16(sb + GA_LO + sw, Alo + ao);
            cp_async16(sb + GB_HI + sw, Bhi + bo);
            cp_async16(sb + GB_LO + sw, Blo + bo);
        }
    };

    load_stage(0, 0);
    CP_COMMIT();

    const int NT = K / 64;
#pragma unroll 1
    for (int t = 0; t < NT; t++) {
        const int buf = t & 1;
        if (t + 1 < NT) {
            load_stage(t + 1, (t + 1) & 1);
            CP_COMMIT();
            CP_WAIT(1);
        } else {
            CP_WAIT(0);
        }
        __syncthreads();

        const uint32_t sb = sbase + buf * GSTAGE;
        const int arow = wm * 64 + (lane & 15);
        const int brow = wn * 32 + (lane & 15);
#pragma unroll
        for (int ks = 0; ks < 4; ks++) {
            const int ch = ks * 2 + (lane >> 4);
            uint32_t ah[4][4], al[4][4];
#pragma unroll
            for (int mt = 0; mt < 4; mt++) {
                uint32_t sw = swz(arow + mt * 16, ch);
                ldsm4(ah[mt], sb + GA_HI + sw);
                ldsm4(al[mt], sb + GA_LO + sw);
            }
            uint32_t bh[2][4], bl[2][4];
#pragma unroll
            for (int nb = 0; nb < 2; nb++) {
                uint32_t sw = swz(brow + nb * 16, ch);
                ldsm4(bh[nb], sb + GB_HI + sw);
                ldsm4(bl[nb], sb + GB_LO + sw);
            }
#pragma unroll
            for (int mt = 0; mt < 4; mt++)
#pragma unroll
                for (int nt = 0; nt < 4; nt++) {
                    const int nb = nt >> 1, hh = nt & 1;
                    mma16816(acc[mt][nt], ah[mt], bh[nb][hh], bh[nb][2 + hh]);
                    mma16816(acc[mt][nt], ah[mt], bl[nb][hh], bl[nb][2 + hh]);
                    mma16816(acc[mt][nt], al[mt], bh[nb][hh], bh[nb][2 + hh]);
                }
        }
        __syncthreads();
    }

    // Epilogue: c0,c1 -> (row=lane>>2, col=(lane&3)*2 .. +1); c2,c3 -> row+8
#pragma unroll
    for (int mt = 0; mt < 4; mt++) {
#pragma unroll
        for (int nt = 0; nt < 4; nt++) {
            int row = m0 + wm * 64 + mt * 16 + (lane >> 2);
            int col = n0 + wn * 32 + nt * 8 + (lane & 3) * 2;
            float2 v0, v1;
            v0.x = acc[mt][nt][0]; v0.y = acc[mt][nt][1];
            v1.x = acc[mt][nt][2]; v1.y = acc[mt][nt][3];
            if (bias) {
                float b0 = bias[col], b1 = bias[col + 1];
                v0.x += b0; v0.y += b1;
                v1.x += b0; v1.y += b1;
            }
            *(float2*)(out + (size_t)row * N + col)       = v0;
            *(float2*)(out + (size_t)(row + 8) * N + col) = v1;
        }
    }
}

// ---------------------------------------------------------------------------
// Fused attention (unchanged from R3 — packed f32x2)
// ---------------------------------------------------------------------------
#define ATT_SMEM ((68*(128+64+64+128) + 128)*4)

__global__ __launch_bounds__(256, 1)
void attention_kernel(const void* __restrict__ mask, float* __restrict__ resT)
{
    extern __shared__ float sm[];
    float* smQ  = sm;
    float* smK  = smQ  + 128 * 68;
    float* smVt = smK  + 64 * 68;
    float* smP  = smVt + 64 * 68;
    float* smD  = smP  + 128 * 68;

    const int tid = threadIdx.x;
    const int blk = blockIdx.x;
    const int qt  = blk & 15;
    const int h   = (blk >> 4) & 15;
    const int b   = blk >> 8;
    const int q0  = qt * 128;
    const int mk  = g_mask_kind;

    const size_t headBase = (size_t)b * Sq * Dq + (size_t)h * Sq * DHq;
    const float* Qh = g_Q + headBase;
    const float* Kh = g_K + headBase;
    const float* Vh = g_V + headBase;

#pragma unroll
    for (int l = 0; l < 8; l++) {
        int idx = l * 256 + tid;
        int row = idx >> 4;
        int dqo = (idx & 15) * 4;
        float4 v = *(const float4*)(Qh + (size_t)(q0 + row) * DHq + dqo);
        v.x *= 0.125f; v.y *= 0.125f; v.z *= 0.125f; v.w *= 0.125f;
        *(float4*)&smQ[row * 68 + dqo] = v;
    }
    if (tid < 128) smD[tid] = 0.f;

#pragma unroll
    for (int l = 0; l < 4; l++) {
        int idx  = l * 256 + tid;
        int krow = idx >> 4, kc = (idx & 15) * 4;
        *(float4*)&smK[krow * 68 + kc] =
            *(const float4*)(Kh + (size_t)krow * DHq + kc);
        int vk = idx & 63, vc = (idx >> 6) * 4;
        float4 vv = *(const float4*)(Vh + (size_t)vk * DHq + vc);
        smVt[(vc + 0) * 68 + vk] = vv.x;
        smVt[(vc + 1) * 68 + vk] = vv.y;
        smVt[(vc + 2) * 68 + vk] = vv.z;
        smVt[(vc + 3) * 68 + vk] = vv.w;
    }
    __syncthreads();

    const int rg = tid >> 3;
    const int cg = tid & 7;

    u64 o2[4][8];
#pragma unroll
    for (int i = 0; i < 4; i++)
#pragma unroll
        for (int t = 0; t < 8; t++) o2[i][t] = 0ull;

#pragma unroll 1
    for (int kt = 0; kt < Sq / 64; kt++) {
        float4 kr[4], vr[4];
        const bool have = (kt + 1 < Sq / 64);
        if (have) {
            const float* Kn = Kh + (size_t)(kt + 1) * 64 * DHq;
            const float* Vn = Vh + (size_t)(kt + 1) * 64 * DHq;
#pragma unroll
            for (int l = 0; l < 4; l++) {
                int idx = l * 256 + tid;
                kr[l] = *(const float4*)(Kn + (size_t)(idx >> 4) * DHq + (idx & 15) * 4);
                vr[l] = *(const float4*)(Vn + (size_t)(idx & 63) * DHq + ((idx >> 6) * 4));
            }
        }

        u64 s2[4][8];
#pragma unroll
        for (int i = 0; i < 4; i++)
#pragma unroll
            for (int t = 0; t < 8; t++) s2[i][t] = 0ull;

#pragma unroll
        for (int q = 0; q < 16; q++) {
            ulonglong2 a[4];
#pragma unroll
            for (int i = 0; i < 4; i++)
                a[i] = *(const ulonglong2*)&smQ[(rg * 4 + i) * 68 + q * 4];
#pragma unroll
            for (int t = 0; t < 8; t++) {
                ulonglong2 kk = *(const ulonglong2*)&smK[(cg + 8 * t) * 68 + q * 4];
#pragma unroll
                for (int i = 0; i < 4; i++) {
                    fma2(s2[i][t], a[i].x, kk.x);
                    fma2(s2[i][t], a[i].y, kk.y);
                }
            }
        }

        const int k0 = kt * 64;
#pragma unroll
        for (int i = 0; i < 4; i++) {
            int qrow = q0 + rg * 4 + i;
            size_t mbase = (size_t)b * Sq * Sq + (size_t)qrow * Sq + k0 + cg;
            float* prow = &smP[(rg * 4 + i) * 68 + cg];
#pragma unroll
            for (int t = 0; t < 8; t++) {
                float2 sp = u2f(s2[i][t]);
                float sv = sp.x + sp.y;
                bool vis;
                if (mk == 0)      vis = ((const unsigned char*)mask)[mbase + 8 * t] != 0;
                else if (mk == 1) vis = ((const int*)mask)[mbase + 8 * t] != 0;
                else              vis = ((const float*)mask)[mbase + 8 * t] != 0.f;
                prow[8 * t] = vis ? __expf(sv) : 0.f;
            }
        }
        __syncthreads();

        if (tid < 128) {
            float ssum = 0.f;
#pragma unroll
            for (int jq = 0; jq < 16; jq++) {
                float4 v = *(const float4*)&smP[tid * 68 + jq * 4];
                ssum += v.x + v.y + v.z + v.w;
            }
            smD[tid] += ssum;
        }

#pragma unroll
        for (int q = 0; q < 16; q++) {
            ulonglong2 pp[4];
#pragma unroll
            for (int i = 0; i < 4; i++)
                pp[i] = *(const ulonglong2*)&smP[(rg * 4 + i) * 68 + q * 4];
#pragma unroll
            for (int t = 0; t < 8; t++) {
                ulonglong2 vv = *(const ulonglong2*)&smVt[(cg + 8 * t) * 68 + q * 4];
#pragma unroll
                for (int i = 0; i < 4; i++) {
                    fma2(o2[i][t], pp[i].x, vv.x);
                    fma2(o2[i][t], pp[i].y, vv.y);
                }
            }
        }
        __syncthreads();

        if (have) {
#pragma unroll
            for (int l = 0; l < 4; l++) {
                int idx = l * 256 + tid;
                *(float4*)&smK[(idx >> 4) * 68 + (idx & 15) * 4] = kr[l];
                int vk = idx & 63, vc = (idx >> 6) * 4;
                smVt[(vc + 0) * 68 + vk] = vr[l].x;
                smVt[(vc + 1) * 68 + vk] = vr[l].y;
                smVt[(vc + 2) * 68 + vk] = vr[l].z;
                smVt[(vc + 3) * 68 + vk] = vr[l].w;
            }
            __syncthreads();
        }
    }

#pragma unroll
    for (int i = 0; i < 4; i++) {
        int r = rg * 4 + i;
        float dn  = smD[r];
        float inv = dn > 0.f ? 1.f / dn : 0.f;
        int s2r = q0 + r;
#pragma unroll
        for (int t = 0; t < 8; t++) {
            float2 ov = u2f(o2[i][t]);
            float val = (ov.x + ov.y) * inv;
            int c = cg + 8 * t;
            g_C[((size_t)b * Sq + s2r) * Dq + h * DHq + c] = val;
            if (resT)
                resT[(((size_t)h * Bq + b) * Sq + s2r) * DHq + c] = val;
        }
    }
}

// ---------------------------------------------------------------------------
extern "C" void kernel_launch(void* const* d_in, const int* in_sizes, int n_in,
                              void* d_out, int out_size)
{
    const float* query = (const float*)d_in[0];
    const float* key_  = (const float*)d_in[1];
    const float* value = (const float*)d_in[2];
    const void*  mask  = d_in[3];
    const float* Wq    = (const float*)d_in[4];
    const float* Wk    = (const float*)d_in[5];
    const float* Wv    = (const float*)d_in[6];
    const float* fcw   = (const float*)d_in[7];
    const float* fcb   = (const float*)d_in[8];
    float* out = (float*)d_out;

    float *dQ, *dK, *dV, *dC;
    cudaGetSymbolAddress((void**)&dQ, g_Q);
    cudaGetSymbolAddress((void**)&dK, g_K);
    cudaGetSymbolAddress((void**)&dV, g_V);
    cudaGetSymbolAddress((void**)&dC, g_C);
    __nv_bfloat16 *xhi, *xlo, *whi, *wlo;
    cudaGetSymbolAddress((void**)&xhi, g_xhi);
    cudaGetSymbolAddress((void**)&xlo, g_xlo);
    cudaGetSymbolAddress((void**)&whi, g_whi);
    cudaGetSymbolAddress((void**)&wlo, g_wlo);

    cudaFuncSetAttribute(gemm_tc_kernel,
                         cudaFuncAttributeMaxDynamicSharedMemorySize, GSMEM);
    cudaFuncSetAttribute(attention_kernel,
                         cudaFuncAttributeMaxDynamicSharedMemorySize, ATT_SMEM);

    detect_mask_kernel<<<1, 32>>>((const unsigned char*)mask);

    const int M = Bq * Sq;               // 8192
    dim3 gtc(Dq / 128, M / 128);         // (8, 64)
    const int nX = M * Dq, nW = Dq * Dq;
    const int bX = nX / 4 / 256, bW = nW / 4 / 256;

    split_kernel<<<bX, 256>>>(query, xhi, xlo, nX);
    split_kernel<<<bW, 256>>>(Wq, whi, wlo, nW);
    gemm_tc_kernel<<<gtc, 256, GSMEM>>>(xhi, xlo, whi, wlo, nullptr, dQ, M, Dq, Dq);

    split_kernel<<<bX, 256>>>(key_, xhi, xlo, nX);
    split_kernel<<<bW, 256>>>(Wk, whi, wlo, nW);
    gemm_tc_kernel<<<gtc, 256, GSMEM>>>(xhi, xlo, whi, wlo, nullptr, dK, M, Dq, Dq);

    split_kernel<<<bX, 256>>>(value, xhi, xlo, nX);
    split_kernel<<<bW, 256>>>(Wv, whi, wlo, nW);
    gemm_tc_kernel<<<gtc, 256, GSMEM>>>(xhi, xlo, whi, wlo, nullptr, dV, M, Dq, Dq);

    float* resT = (out_size >= 2 * BSDq) ? (out + BSDq) : nullptr;
    attention_kernel<<<Bq * Hq * (Sq / 128), 256, ATT_SMEM>>>(mask, resT);

    split_kernel<<<bX, 256>>>(dC, xhi, xlo, nX);
    split_kernel<<<bW, 256>>>(fcw, whi, wlo, nW);
    gemm_tc_kernel<<<gtc, 256, GSMEM>>>(xhi, xlo, whi, wlo, fcb, out, M, Dq, Dq);
}

// round 6
// speedup vs baseline: 3.9352x; 1.5002x over previous
#include <cuda_runtime.h>
#include <cuda_bf16.h>
#include <cstdint>
#include <cstddef>

// Problem constants
#define Bq   4
#define Sq   2048
#define Dq   1024
#define Hq   16
#define DHq  64
#define BSDq (Bq*Sq*Dq)   // 8388608

typedef unsigned long long u64;

// ---------------- generic-PTX tensor-core helpers (sm_80+ ISA) -------------
__device__ __forceinline__ uint32_t smem_u32(const void* p) {
    uint32_t a;
    asm("{ .reg .u64 t; cvta.to.shared.u64 t, %1; cvt.u32.u64 %0, t; }"
        : "=r"(a) : "l"(p));
    return a;
}
__device__ __forceinline__ void cp_async16(uint32_t s, const void* g) {
    asm volatile("cp.async.cg.shared.global [%0], [%1], 16;" :: "r"(s), "l"(g));
}
#define CP_COMMIT() asm volatile("cp.async.commit_group;" ::: "memory")
#define CP_WAIT(n)  asm volatile("cp.async.wait_group %0;" :: "n"(n) : "memory")

__device__ __forceinline__ void ldsm4(uint32_t* r, uint32_t addr) {
    asm volatile("ldmatrix.sync.aligned.m8n8.x4.shared.b16 {%0,%1,%2,%3}, [%4];"
                 : "=r"(r[0]), "=r"(r[1]), "=r"(r[2]), "=r"(r[3]) : "r"(addr));
}
__device__ __forceinline__ void ldsm4t(uint32_t* r, uint32_t addr) {
    asm volatile("ldmatrix.sync.aligned.m8n8.x4.trans.shared.b16 {%0,%1,%2,%3}, [%4];"
                 : "=r"(r[0]), "=r"(r[1]), "=r"(r[2]), "=r"(r[3]) : "r"(addr));
}
// D(f32) += A(bf16) * B(bf16); m16n8k16 row.col
__device__ __forceinline__ void mma16816(float* d, const uint32_t* a,
                                         uint32_t b0, uint32_t b1) {
    asm volatile(
        "mma.sync.aligned.m16n8k16.row.col.f32.bf16.bf16.f32 "
        "{%0,%1,%2,%3}, {%4,%5,%6,%7}, {%8,%9}, {%0,%1,%2,%3};"
        : "+f"(d[0]), "+f"(d[1]), "+f"(d[2]), "+f"(d[3])
        : "r"(a[0]), "r"(a[1]), "r"(a[2]), "r"(a[3]), "r"(b0), "r"(b1));
}
// byte offset of (row, 16B-chunk) in a [rows][64 bf16] tile, xor swizzle
__device__ __forceinline__ uint32_t swz(int row, int ch) {
    uint32_t off = (uint32_t)(row * 128 + ch * 16);
    return off ^ (((uint32_t)row & 7u) << 4);
}

// ---------------- scratch (device globals: allocation-free rule) -----------
__device__ int g_mask_kind;
__device__ __align__(16) __nv_bfloat16 g_qh[BSDq];
__device__ __align__(16) __nv_bfloat16 g_ql[BSDq];
__device__ __align__(16) __nv_bfloat16 g_kh[BSDq];
__device__ __align__(16) __nv_bfloat16 g_kl[BSDq];
__device__ __align__(16) __nv_bfloat16 g_vh[BSDq];
__device__ __align__(16) __nv_bfloat16 g_vl[BSDq];
__device__ __align__(16) __nv_bfloat16 g_xhi[BSDq];
__device__ __align__(16) __nv_bfloat16 g_xlo[BSDq];
__device__ __align__(16) __nv_bfloat16 g_whi[Dq * Dq];
__device__ __align__(16) __nv_bfloat16 g_wlo[Dq * Dq];

// ---------------------------------------------------------------------------
__global__ void detect_mask_kernel(const unsigned char* __restrict__ m) {
    if (threadIdx.x != 0) return;
    int c0 = 0, c1 = 0, c2 = 0, c3 = 0;
    for (int i = 0; i < 4096; i += 4) {
        if (m[i + 0]) c0++;
        if (m[i + 1]) c1++;
        if (m[i + 2]) c2++;
        if (m[i + 3]) c3++;
    }
    int kind;
    if (c1 == 0 && c2 == 0 && c3 == 0) kind = 1;   // int32
    else if (c0 == 0 && c1 == 0)       kind = 2;   // float32
    else                               kind = 0;   // uint8
    g_mask_kind = kind;
}

// fp32 -> bf16 hi/lo split
__global__ __launch_bounds__(256)
void split_kernel(const float* __restrict__ x, __nv_bfloat16* __restrict__ hi,
                  __nv_bfloat16* __restrict__ lo, int n)
{
    int i = (blockIdx.x * 256 + threadIdx.x) * 4;
    if (i >= n) return;
    float4 v = *(const float4*)(x + i);
    __nv_bfloat16 h0 = __float2bfloat16(v.x), h1 = __float2bfloat16(v.y);
    __nv_bfloat16 h2 = __float2bfloat16(v.z), h3 = __float2bfloat16(v.w);
    __nv_bfloat162 hA, hB, lA, lB;
    hA.x = h0; hA.y = h1; hB.x = h2; hB.y = h3;
    lA.x = __float2bfloat16(v.x - __bfloat162float(h0));
    lA.y = __float2bfloat16(v.y - __bfloat162float(h1));
    lB.x = __float2bfloat16(v.z - __bfloat162float(h2));
    lB.y = __float2bfloat16(v.w - __bfloat162float(h3));
    *(__nv_bfloat162*)(hi + i)     = hA;
    *(__nv_bfloat162*)(hi + i + 2) = hB;
    *(__nv_bfloat162*)(lo + i)     = lA;
    *(__nv_bfloat162*)(lo + i + 2) = lB;
}

// ---------------------------------------------------------------------------
// HMMA split-bf16 GEMM: X @ W^T. Output either fp32 (+bias) or split bf16
// hi/lo (with scale) for downstream tensor-core consumers.
// ---------------------------------------------------------------------------
#define GSTAGE  65536
#define GA_HI   0
#define GA_LO   16384
#define GB_HI   32768
#define GB_LO   49152
#define GSMEM   (2*GSTAGE)

__global__ __launch_bounds__(256, 1)
void gemm_tc_kernel(const __nv_bfloat16* __restrict__ Ahi,
                    const __nv_bfloat16* __restrict__ Alo,
                    const __nv_bfloat16* __restrict__ Bhi,
                    const __nv_bfloat16* __restrict__ Blo,
                    const float* __restrict__ bias, float* __restrict__ out32,
                    __nv_bfloat16* __restrict__ outh,
                    __nv_bfloat16* __restrict__ outl, float scale,
                    int M, int N, int K)
{
    extern __shared__ char smem[];
    const uint32_t sbase = smem_u32(smem);
    const int tid  = threadIdx.x;
    const int wid  = tid >> 5;
    const int lane = tid & 31;
    const int m0 = blockIdx.y * 128;
    const int n0 = blockIdx.x * 128;
    const int wm = wid & 1;
    const int wn = wid >> 1;

    float acc[4][4][4];
#pragma unroll
    for (int i = 0; i < 4; i++)
#pragma unroll
        for (int j = 0; j < 4; j++)
#pragma unroll
            for (int c = 0; c < 4; c++) acc[i][j][c] = 0.f;

    int lrow[4], lch[4];
#pragma unroll
    for (int l = 0; l < 4; l++) {
        int idx = l * 256 + tid;
        lrow[l] = idx >> 3;
        lch[l]  = idx & 7;
    }

    auto load_stage = [&](int t, int buf) {
        const int k0 = t * 64;
        const uint32_t sb = sbase + buf * GSTAGE;
#pragma unroll
        for (int l = 0; l < 4; l++) {
            uint32_t sw = swz(lrow[l], lch[l]);
            size_t ao = (size_t)(m0 + lrow[l]) * K + k0 + lch[l] * 8;
            size_t bo = (size_t)(n0 + lrow[l]) * K + k0 + lch[l] * 8;
            cp_async16(sb + GA_HI + sw, Ahi + ao);
            cp_async16(sb + GA_LO + sw, Alo + ao);
            cp_async16(sb + GB_HI + sw, Bhi + bo);
            cp_async16(sb + GB_LO + sw, Blo + bo);
        }
    };

    load_stage(0, 0);
    CP_COMMIT();

    const int NT = K / 64;
#pragma unroll 1
    for (int t = 0; t < NT; t++) {
        const int buf = t & 1;
        if (t + 1 < NT) {
            load_stage(t + 1, (t + 1) & 1);
            CP_COMMIT();
            CP_WAIT(1);
        } else {
            CP_WAIT(0);
        }
        __syncthreads();

        const uint32_t sb = sbase + buf * GSTAGE;
        const int arow = wm * 64 + (lane & 15);
        const int brow = wn * 32 + (lane & 15);
#pragma unroll
        for (int ks = 0; ks < 4; ks++) {
            const int ch = ks * 2 + (lane >> 4);
            uint32_t ah[4][4], al[4][4];
#pragma unroll
            for (int mt = 0; mt < 4; mt++) {
                uint32_t sw = swz(arow + mt * 16, ch);
                ldsm4(ah[mt], sb + GA_HI + sw);
                ldsm4(al[mt], sb + GA_LO + sw);
            }
            uint32_t bh[2][4], bl[2][4];
#pragma unroll
            for (int nb = 0; nb < 2; nb++) {
                uint32_t sw = swz(brow + nb * 16, ch);
                ldsm4(bh[nb], sb + GB_HI + sw);
                ldsm4(bl[nb], sb + GB_LO + sw);
            }
#pragma unroll
            for (int mt = 0; mt < 4; mt++)
#pragma unroll
                for (int nt = 0; nt < 4; nt++) {
                    const int nb = nt >> 1, hh = nt & 1;
                    mma16816(acc[mt][nt], ah[mt], bh[nb][hh], bh[nb][2 + hh]);
                    mma16816(acc[mt][nt], ah[mt], bl[nb][hh], bl[nb][2 + hh]);
                    mma16816(acc[mt][nt], al[mt], bh[nb][hh], bh[nb][2 + hh]);
                }
        }
        __syncthreads();
    }

#pragma unroll
    for (int mt = 0; mt < 4; mt++) {
#pragma unroll
        for (int nt = 0; nt < 4; nt++) {
            int row = m0 + wm * 64 + mt * 16 + (lane >> 2);
            int col = n0 + wn * 32 + nt * 8 + (lane & 3) * 2;
            if (out32) {
                float2 v0, v1;
                v0.x = acc[mt][nt][0]; v0.y = acc[mt][nt][1];
                v1.x = acc[mt][nt][2]; v1.y = acc[mt][nt][3];
                if (bias) {
                    float b0 = bias[col], b1 = bias[col + 1];
                    v0.x += b0; v0.y += b1;
                    v1.x += b0; v1.y += b1;
                }
                *(float2*)(out32 + (size_t)row * N + col)       = v0;
                *(float2*)(out32 + (size_t)(row + 8) * N + col) = v1;
            } else {
#pragma unroll
                for (int rr = 0; rr < 2; rr++) {
                    size_t o = (size_t)(row + rr * 8) * N + col;
                    float x0 = acc[mt][nt][rr * 2 + 0] * scale;
                    float x1 = acc[mt][nt][rr * 2 + 1] * scale;
                    __nv_bfloat162 hv, lv;
                    hv.x = __float2bfloat16(x0);
                    hv.y = __float2bfloat16(x1);
                    lv.x = __float2bfloat16(x0 - __bfloat162float(hv.x));
                    lv.y = __float2bfloat16(x1 - __bfloat162float(hv.y));
                    *(__nv_bfloat162*)(outh + o) = hv;
                    *(__nv_bfloat162*)(outl + o) = lv;
                }
            }
        }
    }
}

// ---------------------------------------------------------------------------
// HMMA flash attention with split-bf16 QK^T and PV, exact-style softmax
// (exp, mask, rowsum, divide; den==0 -> 0). CTA = (b,h,128 q-rows), 8 warps.
// Writes FC input split bf16 (g_xhi/g_xlo) and resT fp32 directly.
// ---------------------------------------------------------------------------
#define AS_QH   0
#define AS_QL   16384
#define AS_K    32768                 // [buf][hi=0/lo=1][8192]
#define AS_V    65536
#define AS_S    98304                 // fp32 [128][68]
#define AS_PH   (98304 + 34816)      // 133120
#define AS_PL   (AS_PH + 16384)      // 149504
#define AS_DEN  (AS_PL + 16384)      // 165888 : 256 floats
#define ATT_SMEM (AS_DEN + 1024)

__global__ __launch_bounds__(256, 1)
void attention_tc_kernel(const void* __restrict__ mask, float* __restrict__ resT,
                         __nv_bfloat16* __restrict__ ctx_h,
                         __nv_bfloat16* __restrict__ ctx_l)
{
    extern __shared__ char smem[];
    const uint32_t sbase = smem_u32(smem);
    float* sS   = (float*)(smem + AS_S);
    float* sDen = (float*)(smem + AS_DEN);

    const int tid  = threadIdx.x;
    const int wid  = tid >> 5;
    const int lane = tid & 31;
    const int wm = wid & 1;        // 2 m-warps (64 q-rows)
    const int wn = wid >> 1;       // 4 n-warps (16 k-cols)
    const int blk = blockIdx.x;
    const int qt  = blk & 15;
    const int h   = (blk >> 4) & 15;
    const int b   = blk >> 8;
    const int q0  = qt * 128;
    const int mk  = g_mask_kind;

    const size_t headBase = (size_t)b * Sq * Dq + (size_t)h * Sq * DHq;
    const __nv_bfloat16* Qh = g_qh + headBase;
    const __nv_bfloat16* Ql = g_ql + headBase;
    const __nv_bfloat16* Kh = g_kh + headBase;
    const __nv_bfloat16* Kl = g_kl + headBase;
    const __nv_bfloat16* Vh = g_vh + headBase;
    const __nv_bfloat16* Vl = g_vl + headBase;

    // ---- initial loads: Q (persistent) + K/V stage 0, all cp.async ----
#pragma unroll
    for (int l = 0; l < 4; l++) {            // Q: 128 rows x 8 chunks
        int idx = l * 256 + tid;
        int row = idx >> 3, ch = idx & 7;
        uint32_t sw = swz(row, ch);
        size_t o = (size_t)(q0 + row) * DHq + ch * 8;
        cp_async16(sbase + AS_QH + sw, Qh + o);
        cp_async16(sbase + AS_QL + sw, Ql + o);
    }
    {
        int idx = tid;                        // K/V stage 0: 64 rows x 8 chunks
#pragma unroll
        for (int l = 0; l < 2; l++) {
            int id2 = l * 256 + idx;
            int row = id2 >> 3, ch = id2 & 7;
            uint32_t sw = swz(row, ch);
            size_t o = (size_t)row * DHq + ch * 8;
            cp_async16(sbase + AS_K + sw,         Kh + o);
            cp_async16(sbase + AS_K + 8192 + sw,  Kl + o);
            cp_async16(sbase + AS_V + sw,         Vh + o);
            cp_async16(sbase + AS_V + 8192 + sw,  Vl + o);
        }
    }
    CP_COMMIT();

    float oacc[4][2][4];
#pragma unroll
    for (int mt = 0; mt < 4; mt++)
#pragma unroll
        for (int nt = 0; nt < 2; nt++)
#pragma unroll
            for (int c = 0; c < 4; c++) oacc[mt][nt][c] = 0.f;
    float denAcc = 0.f;

    const int prow = tid >> 1;           // P-phase: half-row per thread
    const int pcol = (tid & 1) * 32;

    const int NT = Sq / 64;
#pragma unroll 1
    for (int kt = 0; kt < NT; kt++) {
        const int buf = kt & 1;
        CP_WAIT(0);
        __syncthreads();

        // prefetch next K/V stage
        if (kt + 1 < NT) {
            const uint32_t kb = sbase + AS_K + (1 - buf) * 16384;
            const uint32_t vb = sbase + AS_V + (1 - buf) * 16384;
            const size_t gk = (size_t)(kt + 1) * 64 * DHq;
#pragma unroll
            for (int l = 0; l < 2; l++) {
                int id2 = l * 256 + tid;
                int row = id2 >> 3, ch = id2 & 7;
                uint32_t sw = swz(row, ch);
                size_t o = gk + (size_t)row * DHq + ch * 8;
                cp_async16(kb + sw,        Kh + o);
                cp_async16(kb + 8192 + sw, Kl + o);
                cp_async16(vb + sw,        Vh + o);
                cp_async16(vb + 8192 + sw, Vl + o);
            }
            CP_COMMIT();
        }

        // ---- S = Q K^T (3-term split) ----
        float sacc[4][2][4];
#pragma unroll
        for (int mt = 0; mt < 4; mt++)
#pragma unroll
            for (int nt = 0; nt < 2; nt++)
#pragma unroll
                for (int c = 0; c < 4; c++) sacc[mt][nt][c] = 0.f;

        const uint32_t kbh = sbase + AS_K + buf * 16384;
        const uint32_t kbl = kbh + 8192;
        const int arow = wm * 64 + (lane & 15);
        const int brow = wn * 16 + (lane & 15);
#pragma unroll
        for (int ks = 0; ks < 4; ks++) {
            const int ch = ks * 2 + (lane >> 4);
            uint32_t ah[4][4], al[4][4];
#pragma unroll
            for (int mt = 0; mt < 4; mt++) {
                uint32_t sw = swz(arow + mt * 16, ch);
                ldsm4(ah[mt], sbase + AS_QH + sw);
                ldsm4(al[mt], sbase + AS_QL + sw);
            }
            uint32_t bh[4], bl[4];
            {
                uint32_t sw = swz(brow, ch);
                ldsm4(bh, kbh + sw);
                ldsm4(bl, kbl + sw);
            }
#pragma unroll
            for (int mt = 0; mt < 4; mt++)
#pragma unroll
                for (int hh = 0; hh < 2; hh++) {
                    mma16816(sacc[mt][hh], ah[mt], bh[hh], bh[2 + hh]);
                    mma16816(sacc[mt][hh], ah[mt], bl[hh], bl[2 + hh]);
                    mma16816(sacc[mt][hh], al[mt], bh[hh], bh[2 + hh]);
                }
        }

        // ---- store S fragments to smem (fp32) ----
#pragma unroll
        for (int mt = 0; mt < 4; mt++)
#pragma unroll
            for (int nt = 0; nt < 2; nt++) {
                int r0 = wm * 64 + mt * 16 + (lane >> 2);
                int c0 = wn * 16 + nt * 8 + (lane & 3) * 2;
                float2 v0, v1;
                v0.x = sacc[mt][nt][0]; v0.y = sacc[mt][nt][1];
                v1.x = sacc[mt][nt][2]; v1.y = sacc[mt][nt][3];
                *(float2*)&sS[r0 * 68 + c0]       = v0;
                *(float2*)&sS[(r0 + 8) * 68 + c0] = v1;
            }
        __syncthreads();

        // ---- P = mask ? exp(S) : 0 ; row-sums ; split bf16 to smem ----
        {
            const int k0 = kt * 64;
            const size_t mb = (size_t)b * Sq * Sq + (size_t)(q0 + prow) * Sq
                            + k0 + pcol;
#pragma unroll
            for (int chk = 0; chk < 4; chk++) {
                int cb = pcol + chk * 8;
                float4 x0 = *(const float4*)&sS[prow * 68 + cb];
                float4 x1 = *(const float4*)&sS[prow * 68 + cb + 4];
                float p[8];
                p[0] = __expf(x0.x); p[1] = __expf(x0.y);
                p[2] = __expf(x0.z); p[3] = __expf(x0.w);
                p[4] = __expf(x1.x); p[5] = __expf(x1.y);
                p[6] = __expf(x1.z); p[7] = __expf(x1.w);
                if (mk == 0) {
                    u64 mm = *(const u64*)((const unsigned char*)mask + mb + chk * 8);
#pragma unroll
                    for (int j = 0; j < 8; j++)
                        if (((mm >> (8 * j)) & 0xffull) == 0) p[j] = 0.f;
                } else if (mk == 1) {
                    const int* mi = (const int*)mask + mb + chk * 8;
                    int4 a = *(const int4*)mi, c = *(const int4*)(mi + 4);
                    if (!a.x) p[0] = 0.f; if (!a.y) p[1] = 0.f;
                    if (!a.z) p[2] = 0.f; if (!a.w) p[3] = 0.f;
                    if (!c.x) p[4] = 0.f; if (!c.y) p[5] = 0.f;
                    if (!c.z) p[6] = 0.f; if (!c.w) p[7] = 0.f;
                } else {
                    const float* mf = (const float*)mask + mb + chk * 8;
                    float4 a = *(const float4*)mf, c = *(const float4*)(mf + 4);
                    if (a.x == 0.f) p[0] = 0.f; if (a.y == 0.f) p[1] = 0.f;
                    if (a.z == 0.f) p[2] = 0.f; if (a.w == 0.f) p[3] = 0.f;
                    if (c.x == 0.f) p[4] = 0.f; if (c.y == 0.f) p[5] = 0.f;
                    if (c.z == 0.f) p[6] = 0.f; if (c.w == 0.f) p[7] = 0.f;
                }
#pragma unroll
                for (int j = 0; j < 8; j++) denAcc += p[j];
                uint32_t hv[4], lv[4];
#pragma unroll
                for (int j = 0; j < 4; j++) {
                    __nv_bfloat162 h2, l2;
                    h2.x = __float2bfloat16(p[2 * j]);
                    h2.y = __float2bfloat16(p[2 * j + 1]);
                    l2.x = __float2bfloat16(p[2 * j]     - __bfloat162float(h2.x));
                    l2.y = __float2bfloat16(p[2 * j + 1] - __bfloat162float(h2.y));
                    hv[j] = *(uint32_t*)&h2;
                    lv[j] = *(uint32_t*)&l2;
                }
                uint32_t sw = swz(prow, (tid & 1) * 4 + chk);
                *(uint4*)(smem + AS_PH + sw) = *(uint4*)hv;
                *(uint4*)(smem + AS_PL + sw) = *(uint4*)lv;
            }
        }
        __syncthreads();

        // ---- O += P V (3-term split; V via ldmatrix.trans) ----
        const uint32_t vbh = sbase + AS_V + buf * 16384;
        const uint32_t vbl = vbh + 8192;
        // trans ldsm lane mapping: row = ks*16 + (lane&7) + ((lane>>4)<<3),
        // 16B-chunk = wn*2 + ((lane>>3)&1)
        const int vrow0 = (lane & 7) + ((lane >> 4) << 3);
        const int vch   = wn * 2 + ((lane >> 3) & 1);
#pragma unroll
        for (int ks = 0; ks < 4; ks++) {
            const int ch = ks * 2 + (lane >> 4);
            uint32_t ah[4][4], al[4][4];
#pragma unroll
            for (int mt = 0; mt < 4; mt++) {
                uint32_t sw = swz(arow + mt * 16, ch);
                ldsm4(ah[mt], sbase + AS_PH + sw);
                ldsm4(al[mt], sbase + AS_PL + sw);
            }
            uint32_t bh[4], bl[4];
            {
                uint32_t sw = swz(ks * 16 + vrow0, vch);
                ldsm4t(bh, vbh + sw);
                ldsm4t(bl, vbl + sw);
            }
#pragma unroll
            for (int mt = 0; mt < 4; mt++)
#pragma unroll
                for (int hh = 0; hh < 2; hh++) {
                    mma16816(oacc[mt][hh], ah[mt], bh[hh], bh[2 + hh]);
                    mma16816(oacc[mt][hh], ah[mt], bl[hh], bl[2 + hh]);
                    mma16816(oacc[mt][hh], al[mt], bh[hh], bh[2 + hh]);
                }
        }
    }

    // ---- epilogue: normalize, write split context + resT ----
    sDen[tid] = denAcc;
    __syncthreads();

#pragma unroll
    for (int mt = 0; mt < 4; mt++)
#pragma unroll
        for (int nt = 0; nt < 2; nt++)
#pragma unroll
            for (int rr = 0; rr < 2; rr++) {
                int r   = wm * 64 + mt * 16 + (lane >> 2) + rr * 8;
                int col = wn * 16 + nt * 8 + (lane & 3) * 2;
                float dn  = sDen[2 * r] + sDen[2 * r + 1];
                float inv = dn > 0.f ? 1.f / dn : 0.f;     // NaN->0 semantics
                float x0 = oacc[mt][nt][rr * 2 + 0] * inv;
                float x1 = oacc[mt][nt][rr * 2 + 1] * inv;
                int s2 = q0 + r;
                size_t co = ((size_t)b * Sq + s2) * Dq + h * DHq + col;
                __nv_bfloat162 hv, lv;
                hv.x = __float2bfloat16(x0);
                hv.y = __float2bfloat16(x1);
                lv.x = __float2bfloat16(x0 - __bfloat162float(hv.x));
                lv.y = __float2bfloat16(x1 - __bfloat162float(hv.y));
                *(__nv_bfloat162*)(ctx_h + co) = hv;
                *(__nv_bfloat162*)(ctx_l + co) = lv;
                if (resT) {
                    float2 rv; rv.x = x0; rv.y = x1;
                    *(float2*)(resT + (((size_t)h * Bq + b) * Sq + s2) * DHq + col) = rv;
                }
            }
}

// ---------------------------------------------------------------------------
extern "C" void kernel_launch(void* const* d_in, const int* in_sizes, int n_in,
                              void* d_out, int out_size)
{
    const float* query = (const float*)d_in[0];
    const float* key_  = (const float*)d_in[1];
    const float* value = (const float*)d_in[2];
    const void*  mask  = d_in[3];
    const float* Wq    = (const float*)d_in[4];
    const float* Wk    = (const float*)d_in[5];
    const float* Wv    = (const float*)d_in[6];
    const float* fcw   = (const float*)d_in[7];
    const float* fcb   = (const float*)d_in[8];
    float* out = (float*)d_out;

    __nv_bfloat16 *qh, *ql, *kh, *kl, *vh, *vl, *xhi, *xlo, *whi, *wlo;
    cudaGetSymbolAddress((void**)&qh,  g_qh);
    cudaGetSymbolAddress((void**)&ql,  g_ql);
    cudaGetSymbolAddress((void**)&kh,  g_kh);
    cudaGetSymbolAddress((void**)&kl,  g_kl);
    cudaGetSymbolAddress((void**)&vh,  g_vh);
    cudaGetSymbolAddress((void**)&vl,  g_vl);
    cudaGetSymbolAddress((void**)&xhi, g_xhi);
    cudaGetSymbolAddress((void**)&xlo, g_xlo);
    cudaGetSymbolAddress((void**)&whi, g_whi);
    cudaGetSymbolAddress((void**)&wlo, g_wlo);

    cudaFuncSetAttribute(gemm_tc_kernel,
                         cudaFuncAttributeMaxDynamicSharedMemorySize, GSMEM);
    cudaFuncSetAttribute(attention_tc_kernel,
                         cudaFuncAttributeMaxDynamicSharedMemorySize, ATT_SMEM);

    detect_mask_kernel<<<1, 32>>>((const unsigned char*)mask);

    const int M = Bq * Sq;               // 8192
    dim3 gtc(Dq / 128, M / 128);         // (8, 64)
    const int nX = M * Dq, nW = Dq * Dq;
    const int bX = nX / 4 / 256, bW = nW / 4 / 256;

    // Q projection (pre-scaled by 1/8), K, V -> split bf16 outputs
    split_kernel<<<bX, 256>>>(query, xhi, xlo, nX);
    split_kernel<<<bW, 256>>>(Wq, whi, wlo, nW);
    gemm_tc_kernel<<<gtc, 256, GSMEM>>>(xhi, xlo, whi, wlo, nullptr, nullptr,
                                        qh, ql, 0.125f, M, Dq, Dq);

    split_kernel<<<bX, 256>>>(key_, xhi, xlo, nX);
    split_kernel<<<bW, 256>>>(Wk, whi, wlo, nW);
    gemm_tc_kernel<<<gtc, 256, GSMEM>>>(xhi, xlo, whi, wlo, nullptr, nullptr,
                                        kh, kl, 1.0f, M, Dq, Dq);

    split_kernel<<<bX, 256>>>(value, xhi, xlo, nX);
    split_kernel<<<bW, 256>>>(Wv, whi, wlo, nW);
    gemm_tc_kernel<<<gtc, 256, GSMEM>>>(xhi, xlo, whi, wlo, nullptr, nullptr,
                                        vh, vl, 1.0f, M, Dq, Dq);

    // attention writes context split into xhi/xlo + resT fp32
    float* resT = (out_size >= 2 * BSDq) ? (out + BSDq) : nullptr;
    attention_tc_kernel<<<Bq * Hq * (Sq / 128), 256, ATT_SMEM>>>(mask, resT,
                                                                 xhi, xlo);

    // final FC: fp32 out with bias
    split_kernel<<<bW, 256>>>(fcw, whi, wlo, nW);
    gemm_tc_kernel<<<gtc, 256, GSMEM>>>(xhi, xlo, whi, wlo, fcb, out,
                                        nullptr, nullptr, 1.0f, M, Dq, Dq);
}